// round 15
// baseline (speedup 1.0000x reference)
#include <cuda_runtime.h>
#include <cuda_fp16.h>
#include <stdint.h>

// Problem constants
#define B_N 4
#define S_N 2048
#define D_N 1024
#define H_N 16
#define DK_N 64

#define HEAD_EL (8192u * 1024u)        // B*H*S*DK == M*D
#define IN_EL   (3u * HEAD_EL)
#define W_EL    (4u * 1024u * 1024u)

// fp16 scratch (allocation-free) — single-term everywhere
__device__ __half g_inh[IN_EL];                  // q,k,v inputs
__device__ __half g_wh[W_EL];                    // weights
__device__ __half g_qh[HEAD_EL];                 // Q (pre-scaled 0.125*log2e)
__device__ __half g_kh[HEAD_EL];                 // K
__device__ __half g_vh[HEAD_EL];                 // V
__device__ __half g_ch[HEAD_EL];                 // ctx

// ===========================================================================
// Helpers (compute_103-portable: ldmatrix / mma.sync / cp.async)
// ===========================================================================
__device__ __forceinline__ uint32_t smem_u32(const void* p) {
    uint32_t a;
    asm("{ .reg .u64 t; cvta.to.shared.u64 t, %1; cvt.u32.u64 %0, t; }"
        : "=r"(a) : "l"(p));
    return a;
}
__device__ __forceinline__ void ldsm_x4(uint32_t* r, uint32_t addr) {
    asm volatile("ldmatrix.sync.aligned.m8n8.x4.shared.b16 {%0,%1,%2,%3}, [%4];"
        : "=r"(r[0]), "=r"(r[1]), "=r"(r[2]), "=r"(r[3]) : "r"(addr));
}
__device__ __forceinline__ void ldsm_x4t(uint32_t* r, uint32_t addr) {
    asm volatile("ldmatrix.sync.aligned.m8n8.x4.trans.shared.b16 {%0,%1,%2,%3}, [%4];"
        : "=r"(r[0]), "=r"(r[1]), "=r"(r[2]), "=r"(r[3]) : "r"(addr));
}
__device__ __forceinline__ void mma_f32(float* d, const uint32_t* a, const uint32_t* b) {
    asm volatile(
        "mma.sync.aligned.m16n8k16.row.col.f32.f16.f16.f32 "
        "{%0,%1,%2,%3}, {%4,%5,%6,%7}, {%8,%9}, {%0,%1,%2,%3};"
        : "+f"(d[0]), "+f"(d[1]), "+f"(d[2]), "+f"(d[3])
        : "r"(a[0]), "r"(a[1]), "r"(a[2]), "r"(a[3]), "r"(b[0]), "r"(b[1]));
}
__device__ __forceinline__ uint32_t h2pack(float x, float y) {
    union { __half2 h; uint32_t u; } t;
    t.h = __floats2half2_rn(x, y);
    return t.u;
}
__device__ __forceinline__ float2 h2f2(uint32_t u) {
    union { __half2 h; uint32_t u; } t; t.u = u;
    return __half22float2(t.h);
}
__device__ __forceinline__ float ex2(float x) {
    float y;
    asm("ex2.approx.f32 %0, %1;" : "=f"(y) : "f"(x));
    return y;
}
__device__ __forceinline__ uint32_t ex2_h2(uint32_t x) {
    uint32_t y;
    asm("ex2.approx.f16x2 %0, %1;" : "=r"(y) : "r"(x));
    return y;
}
__device__ __forceinline__ void cpa16(uint32_t s, const void* g) {
    asm volatile("cp.async.cg.shared.global [%0], [%1], 16;" :: "r"(s), "l"(g));
}
#define CP_COMMIT() asm volatile("cp.async.commit_group;" ::: "memory")
#define CP_WAIT(n)  asm volatile("cp.async.wait_group %0;" :: "n"(n) : "memory")

// ===========================================================================
// Pre-pass conversions (fp32 -> fp16)
// ===========================================================================
__global__ __launch_bounds__(256) void convert_in(
    const float* __restrict__ q, const float* __restrict__ k,
    const float* __restrict__ v)
{
    const int z = blockIdx.z;
    const float* src = (z == 0) ? q : (z == 1) ? k : v;
    __half* dh = g_inh + (size_t)z * HEAD_EL;
    const int i = blockIdx.x * 256 + threadIdx.x;
    const float4 val = ((const float4*)src)[i];
    ((uint2*)dh)[i] = make_uint2(h2pack(val.x, val.y), h2pack(val.z, val.w));
}

__global__ __launch_bounds__(256) void convert_w(
    const float* __restrict__ wq, const float* __restrict__ wk,
    const float* __restrict__ wv, const float* __restrict__ wo)
{
    const int z = blockIdx.z;
    const float* src = (z == 0) ? wq : (z == 1) ? wk : (z == 2) ? wv : wo;
    __half* dh = g_wh + (size_t)z * 1024 * 1024;
    const int i = blockIdx.x * 256 + threadIdx.x;
    const float4 val = ((const float4*)src)[i];
    ((uint2*)dh)[i] = make_uint2(h2pack(val.x, val.y), h2pack(val.z, val.w));
}

// ===========================================================================
// GEMM: D = A @ W^T (+bias). CTA 128x128, BK=32, 256 thr (8 warps, 32x64),
// single-term fp16, fp32 acc. 3-stage cp.async pipeline, ONE sync/iter.
// __launch_bounds__(256,2): 2 CTAs/SM so fill/epilogue overlap across CTAs.
// Stage: A(10240) | B(10240) = 20480 B. Row stride 80 B.
// ===========================================================================
#define G_BH 10240
#define G_STAGE 20480
#define SMEM_GEMM (3 * G_STAGE) // 61440

__device__ __forceinline__ void gemm_stage_issue(
    uint32_t st, const __half* __restrict__ Ah,
    const __half* __restrict__ Wh, int kt, int tid)
{
    #pragma unroll
    for (int i = 0; i < 2; ++i) {
        const int c = tid + i * 256;             // 0..511
        const int row = c >> 2, ch = c & 3;
        const size_t s = (size_t)row * 1024 + kt * 32 + ch * 8;
        const uint32_t d = st + row * 80 + ch * 16;
        cpa16(d, Ah + s);                         // A
        cpa16(d + G_BH, Wh + s);                  // B
    }
}

template <int MODE>
__device__ __forceinline__ void gemm_h_body(
    const __half* __restrict__ Ah, const __half* __restrict__ Wh,
    const float* __restrict__ bias, float scale,
    float* __restrict__ outf, __half* __restrict__ outh,
    int bm, int bn)
{
    extern __shared__ char smg[];
    const uint32_t sb = smem_u32(smg);
    const int tid = threadIdx.x;
    const int lane = tid & 31;
    const int w = tid >> 5;
    const int wm = w & 3;               // rows wm*32
    const int wn = w >> 2;              // cols wn*64

    const __half* Agh = Ah + (size_t)bm * 128 * 1024;
    const __half* Wgh = Wh + (size_t)bn * 128 * 1024;

    gemm_stage_issue(sb,           Agh, Wgh, 0, tid); CP_COMMIT();
    gemm_stage_issue(sb + G_STAGE, Agh, Wgh, 1, tid); CP_COMMIT();

    float d[2][8][4];
    #pragma unroll
    for (int mi = 0; mi < 2; ++mi)
        #pragma unroll
        for (int ni = 0; ni < 8; ++ni)
            #pragma unroll
            for (int q = 0; q < 4; ++q) d[mi][ni][q] = 0.0f;

    const int arow = wm * 32 + (lane & 15);
    const int akoff = (lane >> 4) << 3;
    const int brow = wn * 64 + (lane & 7) + ((lane & 16) >> 1);
    const int bkoff = ((lane >> 3) & 1) << 3;

    for (int kt = 0; kt < 32; ++kt) {
        if (kt < 31) { CP_WAIT(1); } else { CP_WAIT(0); }
        __syncthreads();
        if (kt + 2 < 32) {
            gemm_stage_issue(sb + (uint32_t)((kt + 2) % 3) * G_STAGE, Agh, Wgh, kt + 2, tid);
            CP_COMMIT();
        }
        const uint32_t st = sb + (uint32_t)(kt % 3) * G_STAGE;
        #pragma unroll
        for (int kk = 0; kk < 32; kk += 16) {
            uint32_t ah[2][4];
            #pragma unroll
            for (int mi = 0; mi < 2; ++mi)
                ldsm_x4(ah[mi], st + (arow + mi * 16) * 80 + (kk + akoff) * 2);
            #pragma unroll
            for (int ni = 0; ni < 8; ni += 2) {
                uint32_t bb[4];
                ldsm_x4(bb, st + G_BH + (brow + ni * 8) * 80 + (kk + bkoff) * 2);
                #pragma unroll
                for (int mi = 0; mi < 2; ++mi) {
                    mma_f32(d[mi][ni],     ah[mi], bb);
                    mma_f32(d[mi][ni + 1], ah[mi], bb + 2);
                }
            }
        }
    }

    // epilogue
    const int r_base = bm * 128 + wm * 32 + (lane >> 2);
    const int c_base = bn * 128 + wn * 64 + 2 * (lane & 3);
    #pragma unroll
    for (int mi = 0; mi < 2; ++mi)
        #pragma unroll
        for (int ni = 0; ni < 8; ++ni) {
            const int col = c_base + ni * 8;
            const float b0 = bias[col], b1 = bias[col + 1];
            #pragma unroll
            for (int rr = 0; rr < 2; ++rr) {
                const int row = r_base + mi * 16 + rr * 8;
                const float vx = (d[mi][ni][rr * 2 + 0] + b0) * scale;
                const float vy = (d[mi][ni][rr * 2 + 1] + b1) * scale;
                if (MODE == 1) {
                    const int bb = row >> 11;
                    const int s = row & (S_N - 1);
                    const int hh = col >> 6;
                    const int dk = col & 63;
                    const size_t idx = (((size_t)(bb * H_N + hh) * S_N + s) * DK_N) + dk;
                    *(uint32_t*)(outh + idx) = h2pack(vx, vy);
                } else {
                    float2 v; v.x = vx; v.y = vy;
                    *(float2*)(outf + (size_t)row * D_N + col) = v;
                }
            }
        }
}

__global__ __launch_bounds__(256, 2) void qkv_proj_mma(
    const float* __restrict__ bq, const float* __restrict__ bk,
    const float* __restrict__ bv)
{
    const int z = blockIdx.z;
    const float* bias = (z == 0) ? bq : (z == 1) ? bk : bv;
    __half* oh = (z == 0) ? g_qh : (z == 1) ? g_kh : g_vh;
    const float scale = (z == 0) ? 0.125f * 1.44269504f : 1.0f;
    gemm_h_body<1>(g_inh + (size_t)z * HEAD_EL,
                   g_wh + (size_t)z * 1024 * 1024,
                   bias, scale, nullptr, oh, blockIdx.y, blockIdx.x);
}

__global__ __launch_bounds__(256, 2) void oproj_mma(
    const float* __restrict__ bo, float* __restrict__ out)
{
    gemm_h_body<0>(g_ch, g_wh + (size_t)3 * 1024 * 1024,
                   bo, 1.0f, out, nullptr, blockIdx.y, blockIdx.x);
}

// ===========================================================================
// Flash attention (R14 + warp-uniform rescale skip):
// CTA = one (b,h) x 256 q-rows, 512 thr (16 warps x 16 rows), 64-key tiles,
// 3-stage cp.async KV pipeline (ONE sync/iter), exp2-domain softmax via
// ex2.approx.f16x2 whose output IS the P fragment; per-lane partial row sums;
// all-ones mask fast path; o/l rescale skipped when no row max changed.
// ===========================================================================
#define F_ST0 36864              // Q = 256*144
#define F_VH 9216                // V offset within stage
#define F_STAGE 18432
#define F_MS (F_ST0 + 3 * F_STAGE)     // 92160
#define F_FLAGS (F_MS + 8192)          // 100352
#define SMEM_FLASH (F_FLAGS + 128)     // 100480

__device__ __forceinline__ void kv_stage_issue(
    uint32_t st, const __half* __restrict__ kh, const __half* __restrict__ vh,
    int t, int tid)
{
    const int c = tid & 511;                // 0..511
    const int row = c >> 3, ch = c & 7;
    const size_t s = ((size_t)t * 64 + row) * 64 + ch * 8;
    const uint32_t d = st + row * 144 + ch * 16;
    cpa16(d, kh + s);
    cpa16(d + F_VH, vh + s);
}

__global__ __launch_bounds__(512, 1)
void flash_mma(const int* __restrict__ mask)
{
    extern __shared__ char smf[];
    const uint32_t sb = smem_u32(smf);
    const int tid = threadIdx.x;
    const int lane = tid & 31;
    const int w = tid >> 5;
    const int bh = blockIdx.y;
    const int q0 = blockIdx.x * 256;
    const int b = bh >> 4;
    const int h = bh & 15;

    const size_t hoff = (size_t)bh * S_N * DK_N;
    const __half* Qh = g_qh + hoff + (size_t)q0 * DK_N;
    const __half* Kh = g_kh + hoff;
    const __half* Vh = g_vh + hoff;
    const int* mg = mask + b * S_N;

    // prologue: Q + mask (group 0), KV stages 0,1 (groups 1,2)
    #pragma unroll
    for (int i = 0; i < 4; ++i) {
        const int c = tid + i * 512;            // 0..2047
        const int row = c >> 3, ch = c & 7;
        cpa16(sb + row * 144 + ch * 16, Qh + (size_t)row * 64 + ch * 8);
    }
    cpa16(sb + F_MS + tid * 16, mg + tid * 4);  // 8192 B
    CP_COMMIT();
    kv_stage_issue(sb + F_ST0,           Kh, Vh, 0, tid); CP_COMMIT();
    kv_stage_issue(sb + F_ST0 + F_STAGE, Kh, Vh, 1, tid); CP_COMMIT();

    float o[8][4];
    #pragma unroll
    for (int vi = 0; vi < 8; ++vi)
        #pragma unroll
        for (int q = 0; q < 4; ++q) o[vi][q] = 0.0f;
    float mst[2] = {-1e30f, -1e30f};
    float lst[2] = {0.0f, 0.0f};     // per-lane partial sums (reduced at end)

    const int qrow = w * 16 + (lane & 15);
    const int qkoff = (lane >> 4) << 3;
    const int brow = (lane & 7) + ((lane & 16) >> 1);
    const int bkoff = ((lane >> 3) & 1) << 3;
    const int vrow = (lane & 7) + (((lane >> 3) & 1) << 3);
    const uint32_t vcoff = (lane & 16) ? 16u : 0u;
    const int c0 = 2 * (lane & 3);
    const int* msk = (const int*)(smf + F_MS);
    const int* flg = (const int*)(smf + F_FLAGS);

    for (int t = 0; t < 32; ++t) {
        if (t < 31) { CP_WAIT(1); } else { CP_WAIT(0); }
        __syncthreads();
        if (t + 2 < 32) {
            kv_stage_issue(sb + F_ST0 + (uint32_t)((t + 2) % 3) * F_STAGE, Kh, Vh, t + 2, tid);
            CP_COMMIT();
        }
        if (t == 0) {
            // per-tile mask flags: tile = 64 ints; warp w covers tiles 2w, 2w+1
            const int j = tid * 4;
            const bool ok = msk[j] && msk[j + 1] && msk[j + 2] && msk[j + 3];
            const unsigned bal = __ballot_sync(0xffffffffu, ok);
            if (lane == 0)  ((int*)(smf + F_FLAGS))[w * 2]     = ((bal & 0xffffu) == 0xffffu);
            if (lane == 16) ((int*)(smf + F_FLAGS))[w * 2 + 1] = ((bal >> 16) == 0xffffu);
            __syncthreads();
        }
        const uint32_t st = sb + F_ST0 + (uint32_t)(t % 3) * F_STAGE;

        // S = Q @ K^T  (16 rows x 64 keys per warp), log2 domain
        float s[8][4];
        #pragma unroll
        for (int ni = 0; ni < 8; ++ni)
            s[ni][0] = s[ni][1] = s[ni][2] = s[ni][3] = 0.0f;

        #pragma unroll
        for (int kc = 0; kc < 4; ++kc) {
            uint32_t qhf[4];
            ldsm_x4(qhf, sb + qrow * 144 + (kc * 16 + qkoff) * 2);
            #pragma unroll
            for (int ni = 0; ni < 8; ni += 2) {
                uint32_t bb[4];
                ldsm_x4(bb, st + (ni * 8 + brow) * 144 + (kc * 16 + bkoff) * 2);
                mma_f32(s[ni],     qhf, bb);
                mma_f32(s[ni + 1], qhf, bb + 2);
            }
        }

        // mask (skipped when the whole tile is nonzero)
        if (!flg[t]) {
            #pragma unroll
            for (int ni = 0; ni < 8; ++ni) {
                if (msk[t * 64 + ni * 8 + c0] == 0)     { s[ni][0] = -1e9f; s[ni][2] = -1e9f; }
                if (msk[t * 64 + ni * 8 + c0 + 1] == 0) { s[ni][1] = -1e9f; s[ni][3] = -1e9f; }
            }
        }

        // online softmax, exp2 domain, f16x2 exp -> P fragments directly.
        // Rescale of o/l is skipped (warp-uniformly) when no row max changed.
        uint32_t sp[8][2];
        float nm0, nm1;
        {
            float mx0 = -1e30f, mx1 = -1e30f;
            #pragma unroll
            for (int ni = 0; ni < 8; ++ni) {
                mx0 = fmaxf(mx0, fmaxf(s[ni][0], s[ni][1]));
                mx1 = fmaxf(mx1, fmaxf(s[ni][2], s[ni][3]));
            }
            mx0 = fmaxf(mx0, __shfl_xor_sync(0xffffffffu, mx0, 1));
            mx0 = fmaxf(mx0, __shfl_xor_sync(0xffffffffu, mx0, 2));
            mx1 = fmaxf(mx1, __shfl_xor_sync(0xffffffffu, mx1, 1));
            mx1 = fmaxf(mx1, __shfl_xor_sync(0xffffffffu, mx1, 2));
            nm0 = fmaxf(mst[0], mx0);
            nm1 = fmaxf(mst[1], mx1);
        }
        const bool changed = (nm0 != mst[0]) || (nm1 != mst[1]);
        if (__any_sync(0xffffffffu, changed)) {
            const float c0r = ex2(mst[0] - nm0);
            const float c1r = ex2(mst[1] - nm1);
            lst[0] *= c0r; lst[1] *= c1r;
            #pragma unroll
            for (int vi = 0; vi < 8; ++vi) {
                o[vi][0] *= c0r; o[vi][1] *= c0r;
                o[vi][2] *= c1r; o[vi][3] *= c1r;
            }
            mst[0] = nm0; mst[1] = nm1;
        }
        {
            float sum0 = 0.0f, sum1 = 0.0f;
            #pragma unroll
            for (int ni = 0; ni < 8; ++ni) {
                const uint32_t p0 = ex2_h2(h2pack(s[ni][0] - mst[0], s[ni][1] - mst[0]));
                const uint32_t p1 = ex2_h2(h2pack(s[ni][2] - mst[1], s[ni][3] - mst[1]));
                sp[ni][0] = p0; sp[ni][1] = p1;
                const float2 f0 = h2f2(p0);
                const float2 f1 = h2f2(p1);
                sum0 += f0.x + f0.y;
                sum1 += f1.x + f1.y;
            }
            lst[0] += sum0; lst[1] += sum1;
        }

        // O += P @ V   (P = sp fragments, already fp16)
        #pragma unroll
        for (int kc = 0; kc < 4; ++kc) {
            uint32_t ph[4];
            ph[0] = sp[2 * kc][0];
            ph[1] = sp[2 * kc][1];
            ph[2] = sp[2 * kc + 1][0];
            ph[3] = sp[2 * kc + 1][1];
            #pragma unroll
            for (int vi = 0; vi < 8; vi += 2) {
                uint32_t vv[4];
                ldsm_x4t(vv, st + F_VH + (kc * 16 + vrow) * 144 + vi * 16 + vcoff);
                mma_f32(o[vi],     ph, vv);
                mma_f32(o[vi + 1], ph, vv + 2);
            }
        }
    }

    // epilogue: reduce l across the 4 lanes of each row, write ctx fp16
    #pragma unroll
    for (int rr = 0; rr < 2; ++rr) {
        float ltot = lst[rr];
        ltot += __shfl_xor_sync(0xffffffffu, ltot, 1);
        ltot += __shfl_xor_sync(0xffffffffu, ltot, 2);
        const float inv = 1.0f / ltot;
        const int r = q0 + w * 16 + (lane >> 2) + rr * 8;
        const size_t base = ((size_t)b * S_N + r) * D_N + h * DK_N;
        #pragma unroll
        for (int vi = 0; vi < 8; ++vi) {
            const int dk = vi * 8 + c0;
            *(uint32_t*)(g_ch + base + dk) =
                h2pack(o[vi][rr * 2] * inv, o[vi][rr * 2 + 1] * inv);
        }
    }
}

// ---------------------------------------------------------------------------
extern "C" void kernel_launch(void* const* d_in, const int* in_sizes, int n_in,
                              void* d_out, int out_size)
{
    (void)in_sizes; (void)n_in; (void)out_size;
    const float* query = (const float*)d_in[0];
    const float* key   = (const float*)d_in[1];
    const float* value = (const float*)d_in[2];
    const int*   mask  = (const int*)d_in[3];
    const float* Wq = (const float*)d_in[4];
    const float* bq = (const float*)d_in[5];
    const float* Wk = (const float*)d_in[6];
    const float* bk = (const float*)d_in[7];
    const float* Wv = (const float*)d_in[8];
    const float* bv = (const float*)d_in[9];
    const float* Wo = (const float*)d_in[10];
    const float* bo = (const float*)d_in[11];
    float* out = (float*)d_out;

    cudaFuncSetAttribute(qkv_proj_mma, cudaFuncAttributeMaxDynamicSharedMemorySize, SMEM_GEMM);
    cudaFuncSetAttribute(oproj_mma,    cudaFuncAttributeMaxDynamicSharedMemorySize, SMEM_GEMM);
    cudaFuncSetAttribute(flash_mma,    cudaFuncAttributeMaxDynamicSharedMemorySize, SMEM_FLASH);

    convert_in<<<dim3(HEAD_EL / 4 / 256, 1, 3), 256>>>(query, key, value);
    convert_w<<<dim3(1024 * 1024 / 4 / 256, 1, 4), 256>>>(Wq, Wk, Wv, Wo);

    qkv_proj_mma<<<dim3(8, 64, 3), 256, SMEM_GEMM>>>(bq, bk, bv);

    // 256-row q-tiles, 8 x 64 = 512 CTAs, 512 threads
    flash_mma<<<dim3(8, B_N * H_N), 512, SMEM_FLASH>>>(mask);

    oproj_mma<<<dim3(8, 64), 256, SMEM_GEMM>>>(bo, out);
}

// round 17
// speedup vs baseline: 1.0117x; 1.0117x over previous
#include <cuda_runtime.h>
#include <cuda_fp16.h>
#include <stdint.h>

// Problem constants
#define B_N 4
#define S_N 2048
#define D_N 1024
#define H_N 16
#define DK_N 64

#define HEAD_EL (8192u * 1024u)        // B*H*S*DK == M*D
#define IN_EL   (3u * HEAD_EL)
#define W_EL    (4u * 1024u * 1024u)

// fp16 scratch (allocation-free) — single-term everywhere
__device__ __half g_inh[IN_EL];                  // q,k,v inputs
__device__ __half g_wh[W_EL];                    // weights
__device__ __half g_qh[HEAD_EL];                 // Q (pre-scaled 0.125*log2e)
__device__ __half g_kh[HEAD_EL];                 // K
__device__ __half g_vh[HEAD_EL];                 // V
__device__ __half g_ch[HEAD_EL];                 // ctx

// ===========================================================================
// Helpers (compute_103-portable: ldmatrix / mma.sync / cp.async)
// ===========================================================================
__device__ __forceinline__ uint32_t smem_u32(const void* p) {
    uint32_t a;
    asm("{ .reg .u64 t; cvta.to.shared.u64 t, %1; cvt.u32.u64 %0, t; }"
        : "=r"(a) : "l"(p));
    return a;
}
__device__ __forceinline__ void ldsm_x4(uint32_t* r, uint32_t addr) {
    asm volatile("ldmatrix.sync.aligned.m8n8.x4.shared.b16 {%0,%1,%2,%3}, [%4];"
        : "=r"(r[0]), "=r"(r[1]), "=r"(r[2]), "=r"(r[3]) : "r"(addr));
}
__device__ __forceinline__ void ldsm_x4t(uint32_t* r, uint32_t addr) {
    asm volatile("ldmatrix.sync.aligned.m8n8.x4.trans.shared.b16 {%0,%1,%2,%3}, [%4];"
        : "=r"(r[0]), "=r"(r[1]), "=r"(r[2]), "=r"(r[3]) : "r"(addr));
}
__device__ __forceinline__ void mma_f32(float* d, const uint32_t* a, const uint32_t* b) {
    asm volatile(
        "mma.sync.aligned.m16n8k16.row.col.f32.f16.f16.f32 "
        "{%0,%1,%2,%3}, {%4,%5,%6,%7}, {%8,%9}, {%0,%1,%2,%3};"
        : "+f"(d[0]), "+f"(d[1]), "+f"(d[2]), "+f"(d[3])
        : "r"(a[0]), "r"(a[1]), "r"(a[2]), "r"(a[3]), "r"(b[0]), "r"(b[1]));
}
__device__ __forceinline__ uint32_t h2pack(float x, float y) {
    union { __half2 h; uint32_t u; } t;
    t.h = __floats2half2_rn(x, y);
    return t.u;
}
__device__ __forceinline__ float2 h2f2(uint32_t u) {
    union { __half2 h; uint32_t u; } t; t.u = u;
    return __half22float2(t.h);
}
__device__ __forceinline__ float ex2(float x) {
    float y;
    asm("ex2.approx.f32 %0, %1;" : "=f"(y) : "f"(x));
    return y;
}
__device__ __forceinline__ uint32_t ex2_h2(uint32_t x) {
    uint32_t y;
    asm("ex2.approx.f16x2 %0, %1;" : "=r"(y) : "r"(x));
    return y;
}
__device__ __forceinline__ void cpa16(uint32_t s, const void* g) {
    asm volatile("cp.async.cg.shared.global [%0], [%1], 16;" :: "r"(s), "l"(g));
}
#define CP_COMMIT() asm volatile("cp.async.commit_group;" ::: "memory")
#define CP_WAIT(n)  asm volatile("cp.async.wait_group %0;" :: "n"(n) : "memory")

// ===========================================================================
// Pre-pass conversions (fp32 -> fp16)
// ===========================================================================
__global__ __launch_bounds__(256) void convert_in(
    const float* __restrict__ q, const float* __restrict__ k,
    const float* __restrict__ v)
{
    const int z = blockIdx.z;
    const float* src = (z == 0) ? q : (z == 1) ? k : v;
    __half* dh = g_inh + (size_t)z * HEAD_EL;
    const int i = blockIdx.x * 256 + threadIdx.x;
    const float4 val = ((const float4*)src)[i];
    ((uint2*)dh)[i] = make_uint2(h2pack(val.x, val.y), h2pack(val.z, val.w));
}

__global__ __launch_bounds__(256) void convert_w(
    const float* __restrict__ wq, const float* __restrict__ wk,
    const float* __restrict__ wv, const float* __restrict__ wo)
{
    const int z = blockIdx.z;
    const float* src = (z == 0) ? wq : (z == 1) ? wk : (z == 2) ? wv : wo;
    __half* dh = g_wh + (size_t)z * 1024 * 1024;
    const int i = blockIdx.x * 256 + threadIdx.x;
    const float4 val = ((const float4*)src)[i];
    ((uint2*)dh)[i] = make_uint2(h2pack(val.x, val.y), h2pack(val.z, val.w));
}

// ===========================================================================
// GEMM: D = A @ W^T (+bias). CTA 128x128, BK=32, 256 thr (8 warps, 32x64),
// single-term fp16, fp32 acc. 3-stage cp.async pipeline, ONE sync/iter.
// __launch_bounds__(256,2): 2 CTAs/SM so fill/epilogue overlap across CTAs.
// Stage: A(10240) | B(10240) = 20480 B. Row stride 80 B.
// ===========================================================================
#define G_BH 10240
#define G_STAGE 20480
#define SMEM_GEMM (3 * G_STAGE) // 61440

__device__ __forceinline__ void gemm_stage_issue(
    uint32_t st, const __half* __restrict__ Ah,
    const __half* __restrict__ Wh, int kt, int tid)
{
    #pragma unroll
    for (int i = 0; i < 2; ++i) {
        const int c = tid + i * 256;             // 0..511
        const int row = c >> 2, ch = c & 3;
        const size_t s = (size_t)row * 1024 + kt * 32 + ch * 8;
        const uint32_t d = st + row * 80 + ch * 16;
        cpa16(d, Ah + s);                         // A
        cpa16(d + G_BH, Wh + s);                  // B
    }
}

template <int MODE>
__device__ __forceinline__ void gemm_h_body(
    const __half* __restrict__ Ah, const __half* __restrict__ Wh,
    const float* __restrict__ bias, float scale,
    float* __restrict__ outf, __half* __restrict__ outh,
    int bm, int bn)
{
    extern __shared__ char smg[];
    const uint32_t sb = smem_u32(smg);
    const int tid = threadIdx.x;
    const int lane = tid & 31;
    const int w = tid >> 5;
    const int wm = w & 3;               // rows wm*32
    const int wn = w >> 2;              // cols wn*64

    const __half* Agh = Ah + (size_t)bm * 128 * 1024;
    const __half* Wgh = Wh + (size_t)bn * 128 * 1024;

    gemm_stage_issue(sb,           Agh, Wgh, 0, tid); CP_COMMIT();
    gemm_stage_issue(sb + G_STAGE, Agh, Wgh, 1, tid); CP_COMMIT();

    float d[2][8][4];
    #pragma unroll
    for (int mi = 0; mi < 2; ++mi)
        #pragma unroll
        for (int ni = 0; ni < 8; ++ni)
            #pragma unroll
            for (int q = 0; q < 4; ++q) d[mi][ni][q] = 0.0f;

    const int arow = wm * 32 + (lane & 15);
    const int akoff = (lane >> 4) << 3;
    const int brow = wn * 64 + (lane & 7) + ((lane & 16) >> 1);
    const int bkoff = ((lane >> 3) & 1) << 3;

    for (int kt = 0; kt < 32; ++kt) {
        if (kt < 31) { CP_WAIT(1); } else { CP_WAIT(0); }
        __syncthreads();
        if (kt + 2 < 32) {
            gemm_stage_issue(sb + (uint32_t)((kt + 2) % 3) * G_STAGE, Agh, Wgh, kt + 2, tid);
            CP_COMMIT();
        }
        const uint32_t st = sb + (uint32_t)(kt % 3) * G_STAGE;
        #pragma unroll
        for (int kk = 0; kk < 32; kk += 16) {
            uint32_t ah[2][4];
            #pragma unroll
            for (int mi = 0; mi < 2; ++mi)
                ldsm_x4(ah[mi], st + (arow + mi * 16) * 80 + (kk + akoff) * 2);
            #pragma unroll
            for (int ni = 0; ni < 8; ni += 2) {
                uint32_t bb[4];
                ldsm_x4(bb, st + G_BH + (brow + ni * 8) * 80 + (kk + bkoff) * 2);
                #pragma unroll
                for (int mi = 0; mi < 2; ++mi) {
                    mma_f32(d[mi][ni],     ah[mi], bb);
                    mma_f32(d[mi][ni + 1], ah[mi], bb + 2);
                }
            }
        }
    }

    // epilogue
    const int r_base = bm * 128 + wm * 32 + (lane >> 2);
    const int c_base = bn * 128 + wn * 64 + 2 * (lane & 3);
    #pragma unroll
    for (int mi = 0; mi < 2; ++mi)
        #pragma unroll
        for (int ni = 0; ni < 8; ++ni) {
            const int col = c_base + ni * 8;
            const float b0 = bias[col], b1 = bias[col + 1];
            #pragma unroll
            for (int rr = 0; rr < 2; ++rr) {
                const int row = r_base + mi * 16 + rr * 8;
                const float vx = (d[mi][ni][rr * 2 + 0] + b0) * scale;
                const float vy = (d[mi][ni][rr * 2 + 1] + b1) * scale;
                if (MODE == 1) {
                    const int bb = row >> 11;
                    const int s = row & (S_N - 1);
                    const int hh = col >> 6;
                    const int dk = col & 63;
                    const size_t idx = (((size_t)(bb * H_N + hh) * S_N + s) * DK_N) + dk;
                    *(uint32_t*)(outh + idx) = h2pack(vx, vy);
                } else {
                    float2 v; v.x = vx; v.y = vy;
                    *(float2*)(outf + (size_t)row * D_N + col) = v;
                }
            }
        }
}

__global__ __launch_bounds__(256, 2) void qkv_proj_mma(
    const float* __restrict__ bq, const float* __restrict__ bk,
    const float* __restrict__ bv)
{
    const int z = blockIdx.z;
    const float* bias = (z == 0) ? bq : (z == 1) ? bk : bv;
    __half* oh = (z == 0) ? g_qh : (z == 1) ? g_kh : g_vh;
    const float scale = (z == 0) ? 0.125f * 1.44269504f : 1.0f;
    gemm_h_body<1>(g_inh + (size_t)z * HEAD_EL,
                   g_wh + (size_t)z * 1024 * 1024,
                   bias, scale, nullptr, oh, blockIdx.y, blockIdx.x);
}

__global__ __launch_bounds__(256, 2) void oproj_mma(
    const float* __restrict__ bo, float* __restrict__ out)
{
    gemm_h_body<0>(g_ch, g_wh + (size_t)3 * 1024 * 1024,
                   bo, 1.0f, out, nullptr, blockIdx.y, blockIdx.x);
}

// ===========================================================================
// Flash attention (exact R14 body — best measured: 248.4 us):
// CTA = one (b,h) x 256 q-rows, 512 thr (16 warps x 16 rows), 64-key tiles,
// 3-stage cp.async KV pipeline (ONE sync/iter), exp2-domain softmax via
// ex2.approx.f16x2 whose output IS the P fragment; per-lane partial row sums;
// all-ones mask fast path. Q persistent in smem (256 x 144 B).
// ===========================================================================
#define F_ST0 36864              // Q = 256*144
#define F_VH 9216                // V offset within stage
#define F_STAGE 18432
#define F_MS (F_ST0 + 3 * F_STAGE)     // 92160
#define F_FLAGS (F_MS + 8192)          // 100352
#define SMEM_FLASH (F_FLAGS + 128)     // 100480

__device__ __forceinline__ void kv_stage_issue(
    uint32_t st, const __half* __restrict__ kh, const __half* __restrict__ vh,
    int t, int tid)
{
    const int c = tid & 511;                // 0..511
    const int row = c >> 3, ch = c & 7;
    const size_t s = ((size_t)t * 64 + row) * 64 + ch * 8;
    const uint32_t d = st + row * 144 + ch * 16;
    cpa16(d, kh + s);
    cpa16(d + F_VH, vh + s);
}

__global__ __launch_bounds__(512, 1)
void flash_mma(const int* __restrict__ mask)
{
    extern __shared__ char smf[];
    const uint32_t sb = smem_u32(smf);
    const int tid = threadIdx.x;
    const int lane = tid & 31;
    const int w = tid >> 5;
    const int bh = blockIdx.y;
    const int q0 = blockIdx.x * 256;
    const int b = bh >> 4;
    const int h = bh & 15;

    const size_t hoff = (size_t)bh * S_N * DK_N;
    const __half* Qh = g_qh + hoff + (size_t)q0 * DK_N;
    const __half* Kh = g_kh + hoff;
    const __half* Vh = g_vh + hoff;
    const int* mg = mask + b * S_N;

    // prologue: Q + mask (group 0), KV stages 0,1 (groups 1,2)
    #pragma unroll
    for (int i = 0; i < 4; ++i) {
        const int c = tid + i * 512;            // 0..2047
        const int row = c >> 3, ch = c & 7;
        cpa16(sb + row * 144 + ch * 16, Qh + (size_t)row * 64 + ch * 8);
    }
    cpa16(sb + F_MS + tid * 16, mg + tid * 4);  // 8192 B
    CP_COMMIT();
    kv_stage_issue(sb + F_ST0,           Kh, Vh, 0, tid); CP_COMMIT();
    kv_stage_issue(sb + F_ST0 + F_STAGE, Kh, Vh, 1, tid); CP_COMMIT();

    float o[8][4];
    #pragma unroll
    for (int vi = 0; vi < 8; ++vi)
        #pragma unroll
        for (int q = 0; q < 4; ++q) o[vi][q] = 0.0f;
    float mst[2] = {-1e30f, -1e30f};
    float lst[2] = {0.0f, 0.0f};     // per-lane partial sums (reduced at end)

    const int qrow = w * 16 + (lane & 15);
    const int qkoff = (lane >> 4) << 3;
    const int brow = (lane & 7) + ((lane & 16) >> 1);
    const int bkoff = ((lane >> 3) & 1) << 3;
    const int vrow = (lane & 7) + (((lane >> 3) & 1) << 3);
    const uint32_t vcoff = (lane & 16) ? 16u : 0u;
    const int c0 = 2 * (lane & 3);
    const int* msk = (const int*)(smf + F_MS);
    const int* flg = (const int*)(smf + F_FLAGS);

    for (int t = 0; t < 32; ++t) {
        if (t < 31) { CP_WAIT(1); } else { CP_WAIT(0); }
        __syncthreads();
        if (t + 2 < 32) {
            kv_stage_issue(sb + F_ST0 + (uint32_t)((t + 2) % 3) * F_STAGE, Kh, Vh, t + 2, tid);
            CP_COMMIT();
        }
        if (t == 0) {
            // per-tile mask flags: tile = 64 ints; warp w covers tiles 2w, 2w+1
            const int j = tid * 4;
            const bool ok = msk[j] && msk[j + 1] && msk[j + 2] && msk[j + 3];
            const unsigned bal = __ballot_sync(0xffffffffu, ok);
            if (lane == 0)  ((int*)(smf + F_FLAGS))[w * 2]     = ((bal & 0xffffu) == 0xffffu);
            if (lane == 16) ((int*)(smf + F_FLAGS))[w * 2 + 1] = ((bal >> 16) == 0xffffu);
            __syncthreads();
        }
        const uint32_t st = sb + F_ST0 + (uint32_t)(t % 3) * F_STAGE;

        // S = Q @ K^T  (16 rows x 64 keys per warp), log2 domain
        float s[8][4];
        #pragma unroll
        for (int ni = 0; ni < 8; ++ni)
            s[ni][0] = s[ni][1] = s[ni][2] = s[ni][3] = 0.0f;

        #pragma unroll
        for (int kc = 0; kc < 4; ++kc) {
            uint32_t qhf[4];
            ldsm_x4(qhf, sb + qrow * 144 + (kc * 16 + qkoff) * 2);
            #pragma unroll
            for (int ni = 0; ni < 8; ni += 2) {
                uint32_t bb[4];
                ldsm_x4(bb, st + (ni * 8 + brow) * 144 + (kc * 16 + bkoff) * 2);
                mma_f32(s[ni],     qhf, bb);
                mma_f32(s[ni + 1], qhf, bb + 2);
            }
        }

        // mask (skipped when the whole tile is nonzero)
        if (!flg[t]) {
            #pragma unroll
            for (int ni = 0; ni < 8; ++ni) {
                if (msk[t * 64 + ni * 8 + c0] == 0)     { s[ni][0] = -1e9f; s[ni][2] = -1e9f; }
                if (msk[t * 64 + ni * 8 + c0 + 1] == 0) { s[ni][1] = -1e9f; s[ni][3] = -1e9f; }
            }
        }

        // online softmax, exp2 domain, f16x2 exp -> P fragments directly
        uint32_t sp[8][2];
        #pragma unroll
        for (int rr = 0; rr < 2; ++rr) {
            float mx = -1e30f;
            #pragma unroll
            for (int ni = 0; ni < 8; ++ni)
                mx = fmaxf(mx, fmaxf(s[ni][rr * 2], s[ni][rr * 2 + 1]));
            mx = fmaxf(mx, __shfl_xor_sync(0xffffffffu, mx, 1));
            mx = fmaxf(mx, __shfl_xor_sync(0xffffffffu, mx, 2));
            const float nm = fmaxf(mst[rr], mx);
            const float corr = ex2(mst[rr] - nm);
            float sum = 0.0f;
            #pragma unroll
            for (int ni = 0; ni < 8; ++ni) {
                const uint32_t p2 = ex2_h2(h2pack(s[ni][rr * 2]     - nm,
                                                  s[ni][rr * 2 + 1] - nm));
                sp[ni][rr] = p2;
                const float2 f = h2f2(p2);
                sum += f.x + f.y;
            }
            lst[rr] = lst[rr] * corr + sum;   // per-lane partial
            mst[rr] = nm;
            #pragma unroll
            for (int vi = 0; vi < 8; ++vi) {
                o[vi][rr * 2]     *= corr;
                o[vi][rr * 2 + 1] *= corr;
            }
        }

        // O += P @ V   (P = sp fragments, already fp16)
        #pragma unroll
        for (int kc = 0; kc < 4; ++kc) {
            uint32_t ph[4];
            ph[0] = sp[2 * kc][0];
            ph[1] = sp[2 * kc][1];
            ph[2] = sp[2 * kc + 1][0];
            ph[3] = sp[2 * kc + 1][1];
            #pragma unroll
            for (int vi = 0; vi < 8; vi += 2) {
                uint32_t vv[4];
                ldsm_x4t(vv, st + F_VH + (kc * 16 + vrow) * 144 + vi * 16 + vcoff);
                mma_f32(o[vi],     ph, vv);
                mma_f32(o[vi + 1], ph, vv + 2);
            }
        }
    }

    // epilogue: reduce l across the 4 lanes of each row, write ctx fp16
    #pragma unroll
    for (int rr = 0; rr < 2; ++rr) {
        float ltot = lst[rr];
        ltot += __shfl_xor_sync(0xffffffffu, ltot, 1);
        ltot += __shfl_xor_sync(0xffffffffu, ltot, 2);
        const float inv = 1.0f / ltot;
        const int r = q0 + w * 16 + (lane >> 2) + rr * 8;
        const size_t base = ((size_t)b * S_N + r) * D_N + h * DK_N;
        #pragma unroll
        for (int vi = 0; vi < 8; ++vi) {
            const int dk = vi * 8 + c0;
            *(uint32_t*)(g_ch + base + dk) =
                h2pack(o[vi][rr * 2] * inv, o[vi][rr * 2 + 1] * inv);
        }
    }
}

// ---------------------------------------------------------------------------
extern "C" void kernel_launch(void* const* d_in, const int* in_sizes, int n_in,
                              void* d_out, int out_size)
{
    (void)in_sizes; (void)n_in; (void)out_size;
    const float* query = (const float*)d_in[0];
    const float* key   = (const float*)d_in[1];
    const float* value = (const float*)d_in[2];
    const int*   mask  = (const int*)d_in[3];
    const float* Wq = (const float*)d_in[4];
    const float* bq = (const float*)d_in[5];
    const float* Wk = (const float*)d_in[6];
    const float* bk = (const float*)d_in[7];
    const float* Wv = (const float*)d_in[8];
    const float* bv = (const float*)d_in[9];
    const float* Wo = (const float*)d_in[10];
    const float* bo = (const float*)d_in[11];
    float* out = (float*)d_out;

    cudaFuncSetAttribute(qkv_proj_mma, cudaFuncAttributeMaxDynamicSharedMemorySize, SMEM_GEMM);
    cudaFuncSetAttribute(oproj_mma,    cudaFuncAttributeMaxDynamicSharedMemorySize, SMEM_GEMM);
    cudaFuncSetAttribute(flash_mma,    cudaFuncAttributeMaxDynamicSharedMemorySize, SMEM_FLASH);

    convert_in<<<dim3(HEAD_EL / 4 / 256, 1, 3), 256>>>(query, key, value);
    convert_w<<<dim3(1024 * 1024 / 4 / 256, 1, 4), 256>>>(Wq, Wk, Wv, Wo);

    qkv_proj_mma<<<dim3(8, 64, 3), 256, SMEM_GEMM>>>(bq, bk, bv);

    // 256-row q-tiles, 8 x 64 = 512 CTAs, 512 threads
    flash_mma<<<dim3(8, B_N * H_N), 512, SMEM_FLASH>>>(mask);

    oproj_mma<<<dim3(8, 64), 256, SMEM_GEMM>>>(bo, out);
}